// round 4
// baseline (speedup 1.0000x reference)
#include <cuda_runtime.h>
#include <math.h>

#define NODE 8192
#define NSEQ 192
#define NN   (NODE + NSEQ)   // 8384
#define CC   128
#define BB   2
#define EE   262144
#define BN   (BB * NN)

// ---------------- static scratch (no allocations allowed) ----------------
__device__ float g_buf0[BB * NN * CC];
__device__ float g_buf1[BB * NN * CC];
__device__ float g_pi[2 * BN];           // double-buffered (layer parity)
__device__ float g_pj[2 * BN];
__device__ float g_dinv_intra[BN];       // (deg_intra+1)^-0.5
__device__ float g_selfnorm[BN];         // 1/(deg_intra+1)
__device__ float g_dinv_inter[BN];       // deg_inter>0 ? 1/deg_inter : 0
__device__ int   g_cntA[BN];
__device__ int   g_cntE[BN];
__device__ int   g_rowA[BB * (NN + 1)];
__device__ int   g_rowE[BB * (NN + 1)];
__device__ int   g_curA[BN];
__device__ int   g_curE[BN];
__device__ int   g_colA[BB * EE];        // intra CSR (by dst): src ids
__device__ int   g_colE[BB * EE];        // inter CSR (by dst): src ids

static inline int cdiv(int a, int b) { return (a + b - 1) / b; }

// ---------------- preprocessing ----------------
// 8 edges per thread; no-return atomics (REDG)
__global__ void k_count(const int* __restrict__ ei) {
    int t = blockIdx.x * blockDim.x + threadIdx.x;
    if (t >= BB * (EE / 8)) return;
    int b = t / (EE / 8), e8 = (t % (EE / 8)) * 8;
    const int* p = ei + (size_t)b * 2 * EE;
    int4 sa = *(const int4*)(p + e8);
    int4 sb = *(const int4*)(p + e8 + 4);
    int4 da = *(const int4*)(p + EE + e8);
    int4 db = *(const int4*)(p + EE + e8 + 4);
    int ss[8] = {sa.x, sa.y, sa.z, sa.w, sb.x, sb.y, sb.z, sb.w};
    int dd[8] = {da.x, da.y, da.z, da.w, db.x, db.y, db.z, db.w};
    int* cA = g_cntA + b * NN;
    int* cE = g_cntE + b * NN;
    #pragma unroll
    for (int k = 0; k < 8; k++) {
        bool same = (ss[k] < NODE) == (dd[k] < NODE);
        atomicAdd(same ? &cA[dd[k]] : &cE[dd[k]], 1);
    }
}

// one block (1024 thr) per batch: 9 items/thread serial + 2-level warp scan
#define SPT 9   // 1024*9 = 9216 >= NN
__global__ void k_scan() {
    int b = blockIdx.x;
    int t = threadIdx.x;
    int lane = t & 31, wid = t >> 5;
    int base = t * SPT;
    int vA[SPT], vE[SPT];
    int sumA = 0, sumE = 0;
    #pragma unroll
    for (int k = 0; k < SPT; k++) {
        int i = base + k;
        int a = (i < NN) ? g_cntA[b * NN + i] : 0;
        int e = (i < NN) ? g_cntE[b * NN + i] : 0;
        vA[k] = a; vE[k] = e; sumA += a; sumE += e;
    }
    // warp inclusive scan of per-thread totals
    int sA = sumA, sE = sumE;
    #pragma unroll
    for (int o = 1; o < 32; o <<= 1) {
        int aA = __shfl_up_sync(0xFFFFFFFFu, sA, o);
        int aE = __shfl_up_sync(0xFFFFFFFFu, sE, o);
        if (lane >= o) { sA += aA; sE += aE; }
    }
    __shared__ int wA[32], wE[32];
    if (lane == 31) { wA[wid] = sA; wE[wid] = sE; }
    __syncthreads();
    if (wid == 0) {
        int a = wA[lane], e = wE[lane];
        #pragma unroll
        for (int o = 1; o < 32; o <<= 1) {
            int aa = __shfl_up_sync(0xFFFFFFFFu, a, o);
            int ee = __shfl_up_sync(0xFFFFFFFFu, e, o);
            if (lane >= o) { a += aa; e += ee; }
        }
        wA[lane] = a; wE[lane] = e;
    }
    __syncthreads();
    int exclA = sA - sumA + (wid ? wA[wid - 1] : 0);
    int exclE = sE - sumE + (wid ? wE[wid - 1] : 0);
    #pragma unroll
    for (int k = 0; k < SPT; k++) {
        int i = base + k;
        if (i < NN) {
            g_rowA[b * (NN + 1) + i] = exclA;  g_curA[b * NN + i] = exclA;
            g_rowE[b * (NN + 1) + i] = exclE;  g_curE[b * NN + i] = exclE;
            float dA = (float)vA[k] + 1.0f;
            g_dinv_intra[b * NN + i] = rsqrtf(dA);
            g_selfnorm[b * NN + i]   = 1.0f / dA;
            g_dinv_inter[b * NN + i] = vE[k] ? 1.0f / (float)vE[k] : 0.0f;
            exclA += vA[k]; exclE += vE[k];
        }
    }
    if (t == 1023) {
        g_rowA[b * (NN + 1) + NN] = exclA;
        g_rowE[b * (NN + 1) + NN] = exclE;
    }
}

// 8 edges per thread for atomic MLP
__global__ void k_fill(const int* __restrict__ ei) {
    int t = blockIdx.x * blockDim.x + threadIdx.x;
    if (t >= BB * (EE / 8)) return;
    int b = t / (EE / 8), e8 = (t % (EE / 8)) * 8;
    const int* p = ei + (size_t)b * 2 * EE;
    int4 sa = *(const int4*)(p + e8);
    int4 sb = *(const int4*)(p + e8 + 4);
    int4 da = *(const int4*)(p + EE + e8);
    int4 db = *(const int4*)(p + EE + e8 + 4);
    int ss[8] = {sa.x, sa.y, sa.z, sa.w, sb.x, sb.y, sb.z, sb.w};
    int dd[8] = {da.x, da.y, da.z, da.w, db.x, db.y, db.z, db.w};
    int* cuA = g_curA + b * NN;
    int* cuE = g_curE + b * NN;
    int pos[8]; bool same[8];
    #pragma unroll
    for (int k = 0; k < 8; k++) {
        same[k] = (ss[k] < NODE) == (dd[k] < NODE);
        pos[k] = atomicAdd(same[k] ? &cuA[dd[k]] : &cuE[dd[k]], 1);
    }
    #pragma unroll
    for (int k = 0; k < 8; k++) {
        (same[k] ? g_colA : g_colE)[b * EE + pos[k]] = ss[k];
    }
}

// ---------------- projection helpers ----------------
__device__ __forceinline__ void proj_epilogue(float4 v, int lane, int n, int w,
                                              const float* Wi_s, const float* Wi_t,
                                              const float* Wj_s, const float* Wj_t,
                                              int wr) {
    const float4* Wi = (const float4*)((n < NODE) ? Wi_s : Wi_t);
    const float4* Wj = (const float4*)((n < NODE) ? Wj_s : Wj_t);
    float4 wi = Wi[lane];
    float4 wj = Wj[lane];
    float si = v.x * wi.x + v.y * wi.y + v.z * wi.z + v.w * wi.w;
    float sj = v.x * wj.x + v.y * wj.y + v.z * wj.z + v.w * wj.w;
    #pragma unroll
    for (int o = 16; o; o >>= 1) {
        si += __shfl_xor_sync(0xFFFFFFFFu, si, o);
        sj += __shfl_xor_sync(0xFFFFFFFFu, sj, o);
    }
    if (lane == 0) { g_pi[wr * BN + w] = si; g_pj[wr * BN + w] = sj; }
}

__global__ void k_proj0(const float* __restrict__ x,
                        const float* __restrict__ Wi_s, const float* __restrict__ Wi_t,
                        const float* __restrict__ Wj_s, const float* __restrict__ Wj_t) {
    int w    = (blockIdx.x * blockDim.x + threadIdx.x) >> 5;
    int lane = threadIdx.x & 31;
    if (w >= BN) return;
    float4 xv = ((const float4*)x)[(size_t)w * 32 + lane];
    proj_epilogue(xv, lane, w % NN, w, Wi_s, Wi_t, Wj_s, Wj_t, 0);
}

// 8-wide unrolled broadcast accumulate
#define GATHER8(K0)                                                          \
    {                                                                        \
        _Pragma("unroll")                                                    \
        for (int u = 0; u < 8; u++) {                                        \
            float c  = __shfl_sync(0xFFFFFFFFu, coef, (K0) + u);             \
            int   sk = __shfl_sync(0xFFFFFFFFu, src,  (K0) + u);             \
            float4 v = xb[(size_t)sk * 32 + lane];                           \
            acc.x += c * v.x; acc.y += c * v.y;                              \
            acc.z += c * v.z; acc.w += c * v.w;                              \
        }                                                                    \
    }

// ---------------- intra: gather + self + residual + relu + next-proj ----------------
__global__ void k_intra(const float* __restrict__ x, float* __restrict__ out,
                        int rd, int wr,
                        const float* __restrict__ Wi_s, const float* __restrict__ Wi_t,
                        const float* __restrict__ Wj_s, const float* __restrict__ Wj_t) {
    int w    = (blockIdx.x * blockDim.x + threadIdx.x) >> 5;
    int lane = threadIdx.x & 31;
    if (w >= BN) return;
    int b = w / NN, n = w % NN;
    const float4* xb = (const float4*)x + (size_t)(b * NN) * 32;
    const float* pjb = g_pj + rd * BN + b * NN;
    const int*   col = g_colA + b * EE;
    float4 xv = xb[(size_t)n * 32 + lane];
    float pid   = g_pi[rd * BN + w];
    float dinvd = g_dinv_intra[w];
    float s = 1.0f + tanhf(pid + pjb[n]) * g_selfnorm[w];
    float4 acc = make_float4(xv.x * s, xv.y * s, xv.z * s, xv.w * s);

    int start = g_rowA[b * (NN + 1) + n];
    int end   = g_rowA[b * (NN + 1) + n + 1];
    const float* dinvA = g_dinv_intra + b * NN;
    for (int e0 = start; e0 < end; e0 += 32) {
        int idx = e0 + lane;
        int src = 0; float coef = 0.0f;
        if (idx < end) {
            src = col[idx];
            coef = tanhf(pid + pjb[src]) * dinvd * dinvA[src];
        }
        int cnt = min(32, end - e0);
        int k = 0;
        for (; k + 8 <= cnt; k += 8) GATHER8(k)
        for (; k < cnt; k++) {
            float c  = __shfl_sync(0xFFFFFFFFu, coef, k);
            int   sk = __shfl_sync(0xFFFFFFFFu, src, k);
            float4 v = xb[(size_t)sk * 32 + lane];
            acc.x += c * v.x; acc.y += c * v.y;
            acc.z += c * v.z; acc.w += c * v.w;
        }
    }
    acc.x = fmaxf(acc.x, 0.0f); acc.y = fmaxf(acc.y, 0.0f);
    acc.z = fmaxf(acc.z, 0.0f); acc.w = fmaxf(acc.w, 0.0f);
    ((float4*)out)[(size_t)w * 32 + lane] = acc;
    proj_epilogue(acc, lane, n, w, Wi_s, Wi_t, Wj_s, Wj_t, wr);
}

// ---------------- inter: gather + residual (+relu, +next-proj) ----------------
__global__ void k_inter(const float* __restrict__ x, float* __restrict__ out,
                        int rd, int wr, int relu_epi,
                        const float* __restrict__ Wi_s, const float* __restrict__ Wi_t,
                        const float* __restrict__ Wj_s, const float* __restrict__ Wj_t) {
    int w    = (blockIdx.x * blockDim.x + threadIdx.x) >> 5;
    int lane = threadIdx.x & 31;
    if (w >= BN) return;
    int b = w / NN, n = w % NN;
    const float4* xb = (const float4*)x + (size_t)(b * NN) * 32;
    const float* pjb = g_pj + rd * BN + b * NN;
    const int*   col = g_colE + b * EE;
    float4 acc = xb[(size_t)n * 32 + lane];

    int start = g_rowE[b * (NN + 1) + n];
    int end   = g_rowE[b * (NN + 1) + n + 1];
    if (start < end) {
        float pid  = g_pi[rd * BN + w];
        float dinv = g_dinv_inter[w];
        for (int e0 = start; e0 < end; e0 += 32) {
            int idx = e0 + lane;
            int src = 0; float coef = 0.0f;
            if (idx < end) {
                src = col[idx];
                coef = tanhf(pid + pjb[src]) * dinv;
            }
            int cnt = min(32, end - e0);
            int k = 0;
            for (; k + 8 <= cnt; k += 8) GATHER8(k)
            for (; k < cnt; k++) {
                float c  = __shfl_sync(0xFFFFFFFFu, coef, k);
                int   sk = __shfl_sync(0xFFFFFFFFu, src, k);
                float4 v = xb[(size_t)sk * 32 + lane];
                acc.x += c * v.x; acc.y += c * v.y;
                acc.z += c * v.z; acc.w += c * v.w;
            }
        }
    }
    if (relu_epi) {
        acc.x = fmaxf(acc.x, 0.0f); acc.y = fmaxf(acc.y, 0.0f);
        acc.z = fmaxf(acc.z, 0.0f); acc.w = fmaxf(acc.w, 0.0f);
    }
    ((float4*)out)[(size_t)w * 32 + lane] = acc;
    if (relu_epi)
        proj_epilogue(acc, lane, n, w, Wi_s, Wi_t, Wj_s, Wj_t, wr);
}

// ---------------- host driver ----------------
extern "C" void kernel_launch(void* const* d_in, const int* in_sizes, int n_in,
                              void* d_out, int out_size) {
    const float* x   = (const float*)d_in[0];
    const int*   ei  = (const int*)d_in[1];
    const float* Wss = (const float*)d_in[2];
    const float* Wtt = (const float*)d_in[3];
    const float* Wst = (const float*)d_in[4];
    const float* Wts = (const float*)d_in[5];
    float* out = (float*)d_out;

    float *b0, *b1;
    int *cntA, *cntE;
    cudaGetSymbolAddress((void**)&b0, g_buf0);
    cudaGetSymbolAddress((void**)&b1, g_buf1);
    cudaGetSymbolAddress((void**)&cntA, g_cntA);
    cudaGetSymbolAddress((void**)&cntE, g_cntE);

    const int TPB = 256;
    const int nOctT = BB * (EE / 8);
    const int nWarpT = BN * 32;

    const float* Wss1 = Wss + 2 * CC;
    const float* Wtt1 = Wtt + 2 * CC;
    const float* Wst1 = Wst + 2 * CC;
    const float* Wts1 = Wts + 2 * CC;

    // --- build CSRs (launch-invariant structure) ---
    cudaMemsetAsync(cntA, 0, BN * sizeof(int));
    cudaMemsetAsync(cntE, 0, BN * sizeof(int));
    k_count<<<cdiv(nOctT, TPB), TPB>>>(ei);
    k_scan <<<BB, 1024>>>();
    k_fill <<<cdiv(nOctT, TPB), TPB>>>(ei);

    // --- layer 0 projections (intra0 weights), parity 0 ---
    k_proj0<<<cdiv(nWarpT, TPB), TPB>>>(x, Wss, Wtt, Wss + CC, Wtt + CC);

    // intra0: read parity 0, write parity 1 (inter0 weights)
    k_intra<<<cdiv(nWarpT, TPB), TPB>>>(x, b0, 0, 1,
                                        Wts, Wst, Wst + CC, Wts + CC);
    // inter0 (+relu): read 1, write 0 (intra1 weights)
    k_inter<<<cdiv(nWarpT, TPB), TPB>>>(b0, b1, 1, 0, 1,
                                        Wss1, Wtt1, Wss1 + CC, Wtt1 + CC);
    // intra1: read 0, write 1 (inter1 weights)
    k_intra<<<cdiv(nWarpT, TPB), TPB>>>(b1, b0, 0, 1,
                                        Wts1, Wst1, Wst1 + CC, Wts1 + CC);
    // inter1 (final, no relu, no epilogue) -> d_out
    k_inter<<<cdiv(nWarpT, TPB), TPB>>>(b0, out, 1, 0, 0,
                                        Wss, Wtt, Wss, Wtt);
}